// round 12
// baseline (speedup 1.0000x reference)
#include <cuda_runtime.h>
#include <cuda_fp16.h>
#include <cstdint>

#define IN_F 256
#define OUT_F 128
#define MAX_NODES 100000
#define BM 128
#define BN 128
#define BK 32

__device__ __half g_hh[(size_t)MAX_NODES * OUT_F];

__device__ __forceinline__ uint32_t f2tf32u(float x) {
    uint32_t o;
    asm("cvt.rna.tf32.f32 %0, %1;" : "=r"(o) : "f"(x));
    return o;
}

__device__ __forceinline__ void mma_tf32(float* c, const uint32_t* a,
                                         uint32_t b0, uint32_t b1) {
    asm volatile(
        "mma.sync.aligned.m16n8k8.row.col.f32.tf32.tf32.f32 "
        "{%0,%1,%2,%3}, {%4,%5,%6,%7}, {%8,%9}, {%0,%1,%2,%3};\n"
        : "+f"(c[0]), "+f"(c[1]), "+f"(c[2]), "+f"(c[3])
        : "r"(a[0]), "r"(a[1]), "r"(a[2]), "r"(a[3]), "r"(b0), "r"(b1));
}

__device__ __forceinline__ void cp_async16(void* smem_dst, const void* gsrc, int src_bytes) {
    uint32_t daddr = (uint32_t)__cvta_generic_to_shared(smem_dst);
    asm volatile("cp.async.ca.shared.global [%0], [%1], 16, %2;\n"
                 :: "r"(daddr), "l"(gsrc), "r"(src_bytes));
}
__device__ __forceinline__ void cp_commit() {
    asm volatile("cp.async.commit_group;\n" ::: "memory");
}
template <int N>
__device__ __forceinline__ void cp_wait() {
    asm volatile("cp.async.wait_group %0;\n" :: "n"(N) : "memory");
}

// ---------------------------------------------------------------------------
// GEMM (exact R10 form, 61us): tf32 mma.sync, 2-stage cp.async pipeline.
// 256 threads = 8 warps (4M x 2N); warp tile 32x64 (2x8 m16n8k8 per k8).
// ---------------------------------------------------------------------------
__global__ __launch_bounds__(256) void gemm_tf32_kernel(
    const float* __restrict__ A,   // [M, 256]
    const float* __restrict__ Bw,  // [256, 128]
    float* __restrict__ C,         // [M, 128]
    int M)
{
    __shared__ float As[2][BM][BK + 4];
    __shared__ float Bs[2][BK][BN + 8];

    const int tid = threadIdx.x;
    const int wid = tid >> 5;
    const int lane = tid & 31;
    const int g = lane >> 2;
    const int t4 = lane & 3;
    const int warp_m = wid & 3;
    const int warp_n = wid >> 2;
    const int row0 = blockIdx.x * BM;

    float c[2][8][4];
#pragma unroll
    for (int mt = 0; mt < 2; mt++)
#pragma unroll
        for (int nt = 0; nt < 8; nt++)
#pragma unroll
            for (int i = 0; i < 4; i++) c[mt][nt][i] = 0.0f;

    const int NITER = IN_F / BK;  // 8

    auto prefetch = [&](int kt, int buf) {
        const int k0 = kt * BK;
#pragma unroll
        for (int t = 0; t < 4; t++) {
            int idx = tid + t * 256;
            int ar = idx >> 3;
            int ac = idx & 7;
            int grow = row0 + ar;
            int ok = (grow < M) ? 16 : 0;
            int gc = (grow < M) ? grow : 0;
            cp_async16(&As[buf][ar][ac * 4],
                       A + (size_t)gc * IN_F + k0 + ac * 4, ok);
        }
#pragma unroll
        for (int t = 0; t < 4; t++) {
            int idx = tid + t * 256;
            int br = idx >> 5;
            int bc = idx & 31;
            cp_async16(&Bs[buf][br][bc * 4],
                       Bw + (size_t)(k0 + br) * OUT_F + bc * 4, 16);
        }
        cp_commit();
    };

    prefetch(0, 0);

    for (int kt = 0; kt < NITER; kt++) {
        const int buf = kt & 1;
        if (kt + 1 < NITER) {
            prefetch(kt + 1, (kt + 1) & 1);
            cp_wait<1>();
        } else {
            cp_wait<0>();
        }
        __syncthreads();

#pragma unroll
        for (int k8 = 0; k8 < 4; k8++) {
            const int k = k8 * 8;
            uint32_t afr[2][4];
#pragma unroll
            for (int mt = 0; mt < 2; mt++) {
                int rb = warp_m * 32 + mt * 16;
                afr[mt][0] = f2tf32u(As[buf][rb + g][k + t4]);
                afr[mt][1] = f2tf32u(As[buf][rb + g + 8][k + t4]);
                afr[mt][2] = f2tf32u(As[buf][rb + g][k + t4 + 4]);
                afr[mt][3] = f2tf32u(As[buf][rb + g + 8][k + t4 + 4]);
            }
#pragma unroll
            for (int nt = 0; nt < 8; nt++) {
                int nb = warp_n * 64 + nt * 8 + g;
                uint32_t b0 = f2tf32u(Bs[buf][k + t4][nb]);
                uint32_t b1 = f2tf32u(Bs[buf][k + t4 + 4][nb]);
                mma_tf32(c[0][nt], afr[0], b0, b1);
                mma_tf32(c[1][nt], afr[1], b0, b1);
            }
        }
        __syncthreads();
    }

    // Epilogue: fp32 to C, fp16 to g_hh.
#pragma unroll
    for (int mt = 0; mt < 2; mt++) {
#pragma unroll
        for (int half = 0; half < 2; half++) {
            int row = row0 + warp_m * 32 + mt * 16 + g + half * 8;
            if (row < M) {
#pragma unroll
                for (int nt = 0; nt < 8; nt++) {
                    int col = warp_n * 64 + nt * 8 + 2 * t4;
                    float x = c[mt][nt][half * 2];
                    float y = c[mt][nt][half * 2 + 1];
                    *reinterpret_cast<float2*>(C + (size_t)row * OUT_F + col) =
                        make_float2(x, y);
                    __half2 hv = __floats2half2_rn(x, y);
                    *reinterpret_cast<__half2*>(g_hh + (size_t)row * OUT_F + col) = hv;
                }
            }
        }
    }
}

// ---------------------------------------------------------------------------
// Edge kernel: 16 lanes per edge, 4 edges per slot per iteration (MLP=8).
// fp16 gather, fp32 math.
// ---------------------------------------------------------------------------
__device__ __forceinline__ float2 h2f(unsigned w) {
    __half2 b = *reinterpret_cast<__half2*>(&w);
    return __half22float2(b);
}

__device__ __forceinline__ float edge_dot(uint4 hu, uint4 hv,
                                          float4 a0, float4 a1) {
    float2 u0 = h2f(hu.x), u1 = h2f(hu.y), u2 = h2f(hu.z), u3 = h2f(hu.w);
    float2 v0 = h2f(hv.x), v1 = h2f(hv.y), v2 = h2f(hv.z), v3 = h2f(hv.w);
    return fabsf(u0.x - v0.x) * a0.x
         + fabsf(u0.y - v0.y) * a0.y
         + fabsf(u1.x - v1.x) * a0.z
         + fabsf(u1.y - v1.y) * a0.w
         + fabsf(u2.x - v2.x) * a1.x
         + fabsf(u2.y - v2.y) * a1.y
         + fabsf(u3.x - v3.x) * a1.z
         + fabsf(u3.y - v3.y) * a1.w;
}

__global__ __launch_bounds__(256) void edge_kernel(
    const int* __restrict__ edge,         // [2,E] int32
    const float* __restrict__ a,          // [128]
    float* __restrict__ ew,               // [E]
    int E)
{
    const int lane = threadIdx.x & 31;
    const int half_id = lane >> 4;
    const int l16 = lane & 15;

    const float4 a0 = *(reinterpret_cast<const float4*>(a) + l16 * 2);
    const float4 a1 = *(reinterpret_cast<const float4*>(a) + l16 * 2 + 1);

    const int warps_total = (gridDim.x * blockDim.x) >> 5;
    const int warp = (blockIdx.x * blockDim.x + threadIdx.x) >> 5;
    const int stride = warps_total * 2;   // edge slots per grid pass

    for (int e = warp * 2 + half_id; e < E; e += 4 * stride) {
        const int e2 = e + stride;
        const int e3 = e + 2 * stride;
        const int e4 = e + 3 * stride;
        const bool has2 = (e2 < E);
        const bool has3 = (e3 < E);
        const bool has4 = (e4 < E);

        int u1 = edge[e];
        int v1 = edge[(size_t)E + e];
        int u2 = has2 ? edge[e2] : u1;
        int v2 = has2 ? edge[(size_t)E + e2] : v1;
        int u3 = has3 ? edge[e3] : u1;
        int v3 = has3 ? edge[(size_t)E + e3] : v1;
        int u4 = has4 ? edge[e4] : u1;
        int v4 = has4 ? edge[(size_t)E + e4] : v1;

        // Issue all 8 gathers before computing (MLP=8)
        uint4 hu1 = *(reinterpret_cast<const uint4*>(g_hh + (size_t)u1 * OUT_F) + l16);
        uint4 hv1 = *(reinterpret_cast<const uint4*>(g_hh + (size_t)v1 * OUT_F) + l16);
        uint4 hu2 = *(reinterpret_cast<const uint4*>(g_hh + (size_t)u2 * OUT_F) + l16);
        uint4 hv2 = *(reinterpret_cast<const uint4*>(g_hh + (size_t)v2 * OUT_F) + l16);
        uint4 hu3 = *(reinterpret_cast<const uint4*>(g_hh + (size_t)u3 * OUT_F) + l16);
        uint4 hv3 = *(reinterpret_cast<const uint4*>(g_hh + (size_t)v3 * OUT_F) + l16);
        uint4 hu4 = *(reinterpret_cast<const uint4*>(g_hh + (size_t)u4 * OUT_F) + l16);
        uint4 hv4 = *(reinterpret_cast<const uint4*>(g_hh + (size_t)v4 * OUT_F) + l16);

        float s1 = edge_dot(hu1, hv1, a0, a1);
        float s2 = edge_dot(hu2, hv2, a0, a1);
        float s3 = edge_dot(hu3, hv3, a0, a1);
        float s4 = edge_dot(hu4, hv4, a0, a1);

#pragma unroll
        for (int off = 8; off > 0; off >>= 1) {
            s1 += __shfl_down_sync(0xFFFFFFFFu, s1, off, 16);
            s2 += __shfl_down_sync(0xFFFFFFFFu, s2, off, 16);
            s3 += __shfl_down_sync(0xFFFFFFFFu, s3, off, 16);
            s4 += __shfl_down_sync(0xFFFFFFFFu, s4, off, 16);
        }

        if (l16 == 0) {
            ew[e] = fmaxf(s1, 0.0f);
            if (has2) ew[e2] = fmaxf(s2, 0.0f);
            if (has3) ew[e3] = fmaxf(s3, 0.0f);
            if (has4) ew[e4] = fmaxf(s4, 0.0f);
        }
    }
}

extern "C" void kernel_launch(void* const* d_in, const int* in_sizes, int n_in,
                              void* d_out, int out_size)
{
    const float* inputs = (const float*)d_in[0];
    const int* edge     = (const int*)d_in[1];
    const float* weight = (const float*)d_in[2];
    const float* a      = (const float*)d_in[3];

    int M = in_sizes[0] / IN_F;        // 100000
    int E = in_sizes[1] / 2;           // 1600000

    float* h  = (float*)d_out;                       // [M,128]
    float* ew = (float*)d_out + (size_t)M * OUT_F;   // [E]

    int gemm_blocks = (M + BM - 1) / BM;             // 782
    gemm_tf32_kernel<<<gemm_blocks, 256>>>(inputs, weight, h, M);

    edge_kernel<<<4096, 256>>>(edge, a, ew, E);
}

// round 13
// speedup vs baseline: 1.0153x; 1.0153x over previous
#include <cuda_runtime.h>
#include <cuda_fp16.h>
#include <cstdint>

#define IN_F 256
#define OUT_F 128
#define MAX_NODES 100000
#define BM 128
#define BN 128
#define BK 32

__device__ __half g_hh[(size_t)MAX_NODES * OUT_F];

__device__ __forceinline__ uint32_t f2tf32u(float x) {
    uint32_t o;
    asm("cvt.rna.tf32.f32 %0, %1;" : "=r"(o) : "f"(x));
    return o;
}

__device__ __forceinline__ void mma_tf32(float* c, const uint32_t* a,
                                         uint32_t b0, uint32_t b1) {
    asm volatile(
        "mma.sync.aligned.m16n8k8.row.col.f32.tf32.tf32.f32 "
        "{%0,%1,%2,%3}, {%4,%5,%6,%7}, {%8,%9}, {%0,%1,%2,%3};\n"
        : "+f"(c[0]), "+f"(c[1]), "+f"(c[2]), "+f"(c[3])
        : "r"(a[0]), "r"(a[1]), "r"(a[2]), "r"(a[3]), "r"(b0), "r"(b1));
}

__device__ __forceinline__ void cp_async16(void* smem_dst, const void* gsrc, int src_bytes) {
    uint32_t daddr = (uint32_t)__cvta_generic_to_shared(smem_dst);
    asm volatile("cp.async.ca.shared.global [%0], [%1], 16, %2;\n"
                 :: "r"(daddr), "l"(gsrc), "r"(src_bytes));
}
__device__ __forceinline__ void cp_commit() {
    asm volatile("cp.async.commit_group;\n" ::: "memory");
}
template <int N>
__device__ __forceinline__ void cp_wait() {
    asm volatile("cp.async.wait_group %0;\n" :: "n"(N) : "memory");
}

// ---------------------------------------------------------------------------
// GEMM: tf32 mma.sync, 2-stage cp.async, SINGLE sync per k-iter.
// Order per iter: wait(all) -> sync -> prefetch(kt+1) -> compute(kt).
// prefetch overwrites buf (kt-1)&1: all its reads finished before this
// iter's barrier. compute reads buf kt&1: its group completed before the
// barrier (wait precedes sync), so cross-thread visibility is ordered.
// ---------------------------------------------------------------------------
__global__ __launch_bounds__(256) void gemm_tf32_kernel(
    const float* __restrict__ A,   // [M, 256]
    const float* __restrict__ Bw,  // [256, 128]
    float* __restrict__ C,         // [M, 128]
    int M)
{
    __shared__ float As[2][BM][BK + 4];
    __shared__ float Bs[2][BK][BN + 8];

    const int tid = threadIdx.x;
    const int wid = tid >> 5;
    const int lane = tid & 31;
    const int g = lane >> 2;
    const int t4 = lane & 3;
    const int warp_m = wid & 3;
    const int warp_n = wid >> 2;
    const int row0 = blockIdx.x * BM;

    float c[2][8][4];
#pragma unroll
    for (int mt = 0; mt < 2; mt++)
#pragma unroll
        for (int nt = 0; nt < 8; nt++)
#pragma unroll
            for (int i = 0; i < 4; i++) c[mt][nt][i] = 0.0f;

    const int NITER = IN_F / BK;  // 8

    auto prefetch = [&](int kt, int buf) {
        const int k0 = kt * BK;
#pragma unroll
        for (int t = 0; t < 4; t++) {
            int idx = tid + t * 256;
            int ar = idx >> 3;
            int ac = idx & 7;
            int grow = row0 + ar;
            int ok = (grow < M) ? 16 : 0;
            int gc = (grow < M) ? grow : 0;
            cp_async16(&As[buf][ar][ac * 4],
                       A + (size_t)gc * IN_F + k0 + ac * 4, ok);
        }
#pragma unroll
        for (int t = 0; t < 4; t++) {
            int idx = tid + t * 256;
            int br = idx >> 5;
            int bc = idx & 31;
            cp_async16(&Bs[buf][br][bc * 4],
                       Bw + (size_t)(k0 + br) * OUT_F + bc * 4, 16);
        }
        cp_commit();
    };

    prefetch(0, 0);

    for (int kt = 0; kt < NITER; kt++) {
        const int buf = kt & 1;
        cp_wait<0>();
        __syncthreads();
        if (kt + 1 < NITER)
            prefetch(kt + 1, (kt + 1) & 1);

#pragma unroll
        for (int k8 = 0; k8 < 4; k8++) {
            const int k = k8 * 8;
            uint32_t afr[2][4];
#pragma unroll
            for (int mt = 0; mt < 2; mt++) {
                int rb = warp_m * 32 + mt * 16;
                afr[mt][0] = f2tf32u(As[buf][rb + g][k + t4]);
                afr[mt][1] = f2tf32u(As[buf][rb + g + 8][k + t4]);
                afr[mt][2] = f2tf32u(As[buf][rb + g][k + t4 + 4]);
                afr[mt][3] = f2tf32u(As[buf][rb + g + 8][k + t4 + 4]);
            }
#pragma unroll
            for (int nt = 0; nt < 8; nt++) {
                int nb = warp_n * 64 + nt * 8 + g;
                uint32_t b0 = f2tf32u(Bs[buf][k + t4][nb]);
                uint32_t b1 = f2tf32u(Bs[buf][k + t4 + 4][nb]);
                mma_tf32(c[0][nt], afr[0], b0, b1);
                mma_tf32(c[1][nt], afr[1], b0, b1);
            }
        }
    }

    // Epilogue: fp32 to C, fp16 to g_hh.
#pragma unroll
    for (int mt = 0; mt < 2; mt++) {
#pragma unroll
        for (int half = 0; half < 2; half++) {
            int row = row0 + warp_m * 32 + mt * 16 + g + half * 8;
            if (row < M) {
#pragma unroll
                for (int nt = 0; nt < 8; nt++) {
                    int col = warp_n * 64 + nt * 8 + 2 * t4;
                    float x = c[mt][nt][half * 2];
                    float y = c[mt][nt][half * 2 + 1];
                    *reinterpret_cast<float2*>(C + (size_t)row * OUT_F + col) =
                        make_float2(x, y);
                    __half2 hv = __floats2half2_rn(x, y);
                    *reinterpret_cast<__half2*>(g_hh + (size_t)row * OUT_F + col) = hv;
                }
            }
        }
    }
}

// ---------------------------------------------------------------------------
// Edge kernel (exact R10 form, 68.2us): 16 lanes/edge, 3 edges per slot
// per iteration (MLP=6). fp16 gather, fp32 math.
// ---------------------------------------------------------------------------
__device__ __forceinline__ float2 h2f(unsigned w) {
    __half2 b = *reinterpret_cast<__half2*>(&w);
    return __half22float2(b);
}

__device__ __forceinline__ float edge_dot(uint4 hu, uint4 hv,
                                          float4 a0, float4 a1) {
    float2 u0 = h2f(hu.x), u1 = h2f(hu.y), u2 = h2f(hu.z), u3 = h2f(hu.w);
    float2 v0 = h2f(hv.x), v1 = h2f(hv.y), v2 = h2f(hv.z), v3 = h2f(hv.w);
    return fabsf(u0.x - v0.x) * a0.x
         + fabsf(u0.y - v0.y) * a0.y
         + fabsf(u1.x - v1.x) * a0.z
         + fabsf(u1.y - v1.y) * a0.w
         + fabsf(u2.x - v2.x) * a1.x
         + fabsf(u2.y - v2.y) * a1.y
         + fabsf(u3.x - v3.x) * a1.z
         + fabsf(u3.y - v3.y) * a1.w;
}

__global__ __launch_bounds__(256) void edge_kernel(
    const int* __restrict__ edge,         // [2,E] int32
    const float* __restrict__ a,          // [128]
    float* __restrict__ ew,               // [E]
    int E)
{
    const int lane = threadIdx.x & 31;
    const int half_id = lane >> 4;
    const int l16 = lane & 15;

    const float4 a0 = *(reinterpret_cast<const float4*>(a) + l16 * 2);
    const float4 a1 = *(reinterpret_cast<const float4*>(a) + l16 * 2 + 1);

    const int warps_total = (gridDim.x * blockDim.x) >> 5;
    const int warp = (blockIdx.x * blockDim.x + threadIdx.x) >> 5;
    const int stride = warps_total * 2;

    for (int e = warp * 2 + half_id; e < E; e += 3 * stride) {
        const int e2 = e + stride;
        const int e3 = e + 2 * stride;
        const bool has2 = (e2 < E);
        const bool has3 = (e3 < E);

        int u1 = edge[e];
        int v1 = edge[(size_t)E + e];
        int u2 = has2 ? edge[e2] : u1;
        int v2 = has2 ? edge[(size_t)E + e2] : v1;
        int u3 = has3 ? edge[e3] : u1;
        int v3 = has3 ? edge[(size_t)E + e3] : v1;

        uint4 hu1 = *(reinterpret_cast<const uint4*>(g_hh + (size_t)u1 * OUT_F) + l16);
        uint4 hv1 = *(reinterpret_cast<const uint4*>(g_hh + (size_t)v1 * OUT_F) + l16);
        uint4 hu2 = *(reinterpret_cast<const uint4*>(g_hh + (size_t)u2 * OUT_F) + l16);
        uint4 hv2 = *(reinterpret_cast<const uint4*>(g_hh + (size_t)v2 * OUT_F) + l16);
        uint4 hu3 = *(reinterpret_cast<const uint4*>(g_hh + (size_t)u3 * OUT_F) + l16);
        uint4 hv3 = *(reinterpret_cast<const uint4*>(g_hh + (size_t)v3 * OUT_F) + l16);

        float s1 = edge_dot(hu1, hv1, a0, a1);
        float s2 = edge_dot(hu2, hv2, a0, a1);
        float s3 = edge_dot(hu3, hv3, a0, a1);

#pragma unroll
        for (int off = 8; off > 0; off >>= 1) {
            s1 += __shfl_down_sync(0xFFFFFFFFu, s1, off, 16);
            s2 += __shfl_down_sync(0xFFFFFFFFu, s2, off, 16);
            s3 += __shfl_down_sync(0xFFFFFFFFu, s3, off, 16);
        }

        if (l16 == 0) {
            ew[e] = fmaxf(s1, 0.0f);
            if (has2) ew[e2] = fmaxf(s2, 0.0f);
            if (has3) ew[e3] = fmaxf(s3, 0.0f);
        }
    }
}

extern "C" void kernel_launch(void* const* d_in, const int* in_sizes, int n_in,
                              void* d_out, int out_size)
{
    const float* inputs = (const float*)d_in[0];
    const int* edge     = (const int*)d_in[1];
    const float* weight = (const float*)d_in[2];
    const float* a      = (const float*)d_in[3];

    int M = in_sizes[0] / IN_F;        // 100000
    int E = in_sizes[1] / 2;           // 1600000

    float* h  = (float*)d_out;                       // [M,128]
    float* ew = (float*)d_out + (size_t)M * OUT_F;   // [E]

    int gemm_blocks = (M + BM - 1) / BM;             // 782
    gemm_tf32_kernel<<<gemm_blocks, 256>>>(inputs, weight, h, M);

    edge_kernel<<<4096, 256>>>(edge, a, ew, E);
}

// round 14
// speedup vs baseline: 1.0824x; 1.0661x over previous
#include <cuda_runtime.h>
#include <cuda_fp16.h>
#include <cstdint>

#define IN_F 256
#define OUT_F 128
#define MAX_NODES 100000
#define BM 128
#define BN 128
#define BK 32
#define EPW 24   // edges per warp per grid pass (12 per 16-lane half)

__device__ __half g_hh[(size_t)MAX_NODES * OUT_F];

__device__ __forceinline__ uint32_t f2tf32u(float x) {
    uint32_t o;
    asm("cvt.rna.tf32.f32 %0, %1;" : "=r"(o) : "f"(x));
    return o;
}

__device__ __forceinline__ void mma_tf32(float* c, const uint32_t* a,
                                         uint32_t b0, uint32_t b1) {
    asm volatile(
        "mma.sync.aligned.m16n8k8.row.col.f32.tf32.tf32.f32 "
        "{%0,%1,%2,%3}, {%4,%5,%6,%7}, {%8,%9}, {%0,%1,%2,%3};\n"
        : "+f"(c[0]), "+f"(c[1]), "+f"(c[2]), "+f"(c[3])
        : "r"(a[0]), "r"(a[1]), "r"(a[2]), "r"(a[3]), "r"(b0), "r"(b1));
}

__device__ __forceinline__ void cp_async16(void* smem_dst, const void* gsrc, int src_bytes) {
    uint32_t daddr = (uint32_t)__cvta_generic_to_shared(smem_dst);
    asm volatile("cp.async.ca.shared.global [%0], [%1], 16, %2;\n"
                 :: "r"(daddr), "l"(gsrc), "r"(src_bytes));
}
__device__ __forceinline__ void cp_commit() {
    asm volatile("cp.async.commit_group;\n" ::: "memory");
}
template <int N>
__device__ __forceinline__ void cp_wait() {
    asm volatile("cp.async.wait_group %0;\n" :: "n"(N) : "memory");
}

// ---------------------------------------------------------------------------
// GEMM (R13 form, ~62us): tf32 mma.sync, 2-stage cp.async, one sync/k-iter.
// ---------------------------------------------------------------------------
__global__ __launch_bounds__(256) void gemm_tf32_kernel(
    const float* __restrict__ A,   // [M, 256]
    const float* __restrict__ Bw,  // [256, 128]
    float* __restrict__ C,         // [M, 128]
    int M)
{
    __shared__ float As[2][BM][BK + 4];
    __shared__ float Bs[2][BK][BN + 8];

    const int tid = threadIdx.x;
    const int wid = tid >> 5;
    const int lane = tid & 31;
    const int g = lane >> 2;
    const int t4 = lane & 3;
    const int warp_m = wid & 3;
    const int warp_n = wid >> 2;
    const int row0 = blockIdx.x * BM;

    float c[2][8][4];
#pragma unroll
    for (int mt = 0; mt < 2; mt++)
#pragma unroll
        for (int nt = 0; nt < 8; nt++)
#pragma unroll
            for (int i = 0; i < 4; i++) c[mt][nt][i] = 0.0f;

    const int NITER = IN_F / BK;  // 8

    auto prefetch = [&](int kt, int buf) {
        const int k0 = kt * BK;
#pragma unroll
        for (int t = 0; t < 4; t++) {
            int idx = tid + t * 256;
            int ar = idx >> 3;
            int ac = idx & 7;
            int grow = row0 + ar;
            int ok = (grow < M) ? 16 : 0;
            int gc = (grow < M) ? grow : 0;
            cp_async16(&As[buf][ar][ac * 4],
                       A + (size_t)gc * IN_F + k0 + ac * 4, ok);
        }
#pragma unroll
        for (int t = 0; t < 4; t++) {
            int idx = tid + t * 256;
            int br = idx >> 5;
            int bc = idx & 31;
            cp_async16(&Bs[buf][br][bc * 4],
                       Bw + (size_t)(k0 + br) * OUT_F + bc * 4, 16);
        }
        cp_commit();
    };

    prefetch(0, 0);

    for (int kt = 0; kt < NITER; kt++) {
        const int buf = kt & 1;
        cp_wait<0>();
        __syncthreads();
        if (kt + 1 < NITER)
            prefetch(kt + 1, (kt + 1) & 1);

#pragma unroll
        for (int k8 = 0; k8 < 4; k8++) {
            const int k = k8 * 8;
            uint32_t afr[2][4];
#pragma unroll
            for (int mt = 0; mt < 2; mt++) {
                int rb = warp_m * 32 + mt * 16;
                afr[mt][0] = f2tf32u(As[buf][rb + g][k + t4]);
                afr[mt][1] = f2tf32u(As[buf][rb + g + 8][k + t4]);
                afr[mt][2] = f2tf32u(As[buf][rb + g][k + t4 + 4]);
                afr[mt][3] = f2tf32u(As[buf][rb + g + 8][k + t4 + 4]);
            }
#pragma unroll
            for (int nt = 0; nt < 8; nt++) {
                int nb = warp_n * 64 + nt * 8 + g;
                uint32_t b0 = f2tf32u(Bs[buf][k + t4][nb]);
                uint32_t b1 = f2tf32u(Bs[buf][k + t4 + 4][nb]);
                mma_tf32(c[0][nt], afr[0], b0, b1);
                mma_tf32(c[1][nt], afr[1], b0, b1);
            }
        }
    }

    // Epilogue: fp32 to C, fp16 to g_hh.
#pragma unroll
    for (int mt = 0; mt < 2; mt++) {
#pragma unroll
        for (int half = 0; half < 2; half++) {
            int row = row0 + warp_m * 32 + mt * 16 + g + half * 8;
            if (row < M) {
#pragma unroll
                for (int nt = 0; nt < 8; nt++) {
                    int col = warp_n * 64 + nt * 8 + 2 * t4;
                    float x = c[mt][nt][half * 2];
                    float y = c[mt][nt][half * 2 + 1];
                    *reinterpret_cast<float2*>(C + (size_t)row * OUT_F + col) =
                        make_float2(x, y);
                    __half2 hv = __floats2half2_rn(x, y);
                    *reinterpret_cast<__half2*>(g_hh + (size_t)row * OUT_F + col) = hv;
                }
            }
        }
    }
}

// ---------------------------------------------------------------------------
// Edge kernel: per warp, 24 consecutive edges. Indices loaded coalesced by
// lanes 0..23 (2 LDG.32 per 24 edges vs 48 broadcast loads), distributed by
// shuffle. Each 16-lane half processes 12 edges in 4 iters of 3 (MLP=6).
// fp16 row gathers, fp32 math — numerics identical to R10.
// ---------------------------------------------------------------------------
__device__ __forceinline__ float2 h2f(unsigned w) {
    __half2 b = *reinterpret_cast<__half2*>(&w);
    return __half22float2(b);
}

__device__ __forceinline__ float edge_dot(uint4 hu, uint4 hv,
                                          float4 a0, float4 a1) {
    float2 u0 = h2f(hu.x), u1 = h2f(hu.y), u2 = h2f(hu.z), u3 = h2f(hu.w);
    float2 v0 = h2f(hv.x), v1 = h2f(hv.y), v2 = h2f(hv.z), v3 = h2f(hv.w);
    return fabsf(u0.x - v0.x) * a0.x
         + fabsf(u0.y - v0.y) * a0.y
         + fabsf(u1.x - v1.x) * a0.z
         + fabsf(u1.y - v1.y) * a0.w
         + fabsf(u2.x - v2.x) * a1.x
         + fabsf(u2.y - v2.y) * a1.y
         + fabsf(u3.x - v3.x) * a1.z
         + fabsf(u3.y - v3.y) * a1.w;
}

__global__ __launch_bounds__(256) void edge_kernel(
    const int* __restrict__ edge,         // [2,E] int32
    const float* __restrict__ a,          // [128]
    float* __restrict__ ew,               // [E]
    int E)
{
    const int lane = threadIdx.x & 31;
    const int half_id = lane >> 4;
    const int l16 = lane & 15;

    const float4 a0 = *(reinterpret_cast<const float4*>(a) + l16 * 2);
    const float4 a1 = *(reinterpret_cast<const float4*>(a) + l16 * 2 + 1);

    const int warps_total = (gridDim.x * blockDim.x) >> 5;
    const int warp = (blockIdx.x * blockDim.x + threadIdx.x) >> 5;

    for (int base = warp * EPW; base < E; base += warps_total * EPW) {
        // Coalesced index load: lanes 0..23 cover this warp's 24 edges.
        int u = 0, v = 0;
        int gidx = base + lane;
        if (lane < EPW && gidx < E) {
            u = edge[gidx];
            v = edge[(size_t)E + gidx];
        }

#pragma unroll
        for (int j3 = 0; j3 < 4; j3++) {
            const int s0 = half_id * 12 + j3 * 3;   // source lane of 1st edge
            const int e0 = base + s0;               // 3 consecutive edges

            int ua = __shfl_sync(0xFFFFFFFFu, u, s0);
            int va = __shfl_sync(0xFFFFFFFFu, v, s0);
            int ub = __shfl_sync(0xFFFFFFFFu, u, s0 + 1);
            int vb = __shfl_sync(0xFFFFFFFFu, v, s0 + 1);
            int uc = __shfl_sync(0xFFFFFFFFu, u, s0 + 2);
            int vc = __shfl_sync(0xFFFFFFFFu, v, s0 + 2);

            // Issue all 6 row gathers before computing (MLP=6)
            uint4 hua = *(reinterpret_cast<const uint4*>(g_hh + (size_t)ua * OUT_F) + l16);
            uint4 hva = *(reinterpret_cast<const uint4*>(g_hh + (size_t)va * OUT_F) + l16);
            uint4 hub = *(reinterpret_cast<const uint4*>(g_hh + (size_t)ub * OUT_F) + l16);
            uint4 hvb = *(reinterpret_cast<const uint4*>(g_hh + (size_t)vb * OUT_F) + l16);
            uint4 huc = *(reinterpret_cast<const uint4*>(g_hh + (size_t)uc * OUT_F) + l16);
            uint4 hvc = *(reinterpret_cast<const uint4*>(g_hh + (size_t)vc * OUT_F) + l16);

            float s1 = edge_dot(hua, hva, a0, a1);
            float s2 = edge_dot(hub, hvb, a0, a1);
            float s3 = edge_dot(huc, hvc, a0, a1);

#pragma unroll
            for (int off = 8; off > 0; off >>= 1) {
                s1 += __shfl_down_sync(0xFFFFFFFFu, s1, off, 16);
                s2 += __shfl_down_sync(0xFFFFFFFFu, s2, off, 16);
                s3 += __shfl_down_sync(0xFFFFFFFFu, s3, off, 16);
            }

            if (l16 == 0) {
                if (e0 < E)     ew[e0]     = fmaxf(s1, 0.0f);
                if (e0 + 1 < E) ew[e0 + 1] = fmaxf(s2, 0.0f);
                if (e0 + 2 < E) ew[e0 + 2] = fmaxf(s3, 0.0f);
            }
        }
    }
}

extern "C" void kernel_launch(void* const* d_in, const int* in_sizes, int n_in,
                              void* d_out, int out_size)
{
    const float* inputs = (const float*)d_in[0];
    const int* edge     = (const int*)d_in[1];
    const float* weight = (const float*)d_in[2];
    const float* a      = (const float*)d_in[3];

    int M = in_sizes[0] / IN_F;        // 100000
    int E = in_sizes[1] / 2;           // 1600000

    float* h  = (float*)d_out;                       // [M,128]
    float* ew = (float*)d_out + (size_t)M * OUT_F;   // [E]

    int gemm_blocks = (M + BM - 1) / BM;             // 782
    gemm_tf32_kernel<<<gemm_blocks, 256>>>(inputs, weight, h, M);

    edge_kernel<<<4096, 256>>>(edge, a, ew, E);
}

// round 15
// speedup vs baseline: 1.0927x; 1.0096x over previous
#include <cuda_runtime.h>
#include <cuda_fp16.h>
#include <cstdint>

#define IN_F 256
#define OUT_F 128
#define MAX_NODES 100000
#define BM 128
#define BN 128
#define BK 32
#define EPW 24   // edges per warp per grid pass (12 per 16-lane half)

__device__ __half g_hh[(size_t)MAX_NODES * OUT_F];

__device__ __forceinline__ uint32_t f2tf32u(float x) {
    uint32_t o;
    asm("cvt.rna.tf32.f32 %0, %1;" : "=r"(o) : "f"(x));
    return o;
}

__device__ __forceinline__ void mma_tf32(float* c, const uint32_t* a,
                                         uint32_t b0, uint32_t b1) {
    asm volatile(
        "mma.sync.aligned.m16n8k8.row.col.f32.tf32.tf32.f32 "
        "{%0,%1,%2,%3}, {%4,%5,%6,%7}, {%8,%9}, {%0,%1,%2,%3};\n"
        : "+f"(c[0]), "+f"(c[1]), "+f"(c[2]), "+f"(c[3])
        : "r"(a[0]), "r"(a[1]), "r"(a[2]), "r"(a[3]), "r"(b0), "r"(b1));
}

__device__ __forceinline__ void cp_async16(void* smem_dst, const void* gsrc, int src_bytes) {
    uint32_t daddr = (uint32_t)__cvta_generic_to_shared(smem_dst);
    asm volatile("cp.async.ca.shared.global [%0], [%1], 16, %2;\n"
                 :: "r"(daddr), "l"(gsrc), "r"(src_bytes));
}
__device__ __forceinline__ void cp_commit() {
    asm volatile("cp.async.commit_group;\n" ::: "memory");
}
template <int N>
__device__ __forceinline__ void cp_wait() {
    asm volatile("cp.async.wait_group %0;\n" :: "n"(N) : "memory");
}

// ---------------------------------------------------------------------------
// GEMM (R13 form, ~62us): tf32 mma.sync, 2-stage cp.async, one sync/k-iter.
// ---------------------------------------------------------------------------
__global__ __launch_bounds__(256) void gemm_tf32_kernel(
    const float* __restrict__ A,   // [M, 256]
    const float* __restrict__ Bw,  // [256, 128]
    float* __restrict__ C,         // [M, 128]
    int M)
{
    __shared__ float As[2][BM][BK + 4];
    __shared__ float Bs[2][BK][BN + 8];

    const int tid = threadIdx.x;
    const int wid = tid >> 5;
    const int lane = tid & 31;
    const int g = lane >> 2;
    const int t4 = lane & 3;
    const int warp_m = wid & 3;
    const int warp_n = wid >> 2;
    const int row0 = blockIdx.x * BM;

    float c[2][8][4];
#pragma unroll
    for (int mt = 0; mt < 2; mt++)
#pragma unroll
        for (int nt = 0; nt < 8; nt++)
#pragma unroll
            for (int i = 0; i < 4; i++) c[mt][nt][i] = 0.0f;

    const int NITER = IN_F / BK;  // 8

    auto prefetch = [&](int kt, int buf) {
        const int k0 = kt * BK;
#pragma unroll
        for (int t = 0; t < 4; t++) {
            int idx = tid + t * 256;
            int ar = idx >> 3;
            int ac = idx & 7;
            int grow = row0 + ar;
            int ok = (grow < M) ? 16 : 0;
            int gc = (grow < M) ? grow : 0;
            cp_async16(&As[buf][ar][ac * 4],
                       A + (size_t)gc * IN_F + k0 + ac * 4, ok);
        }
#pragma unroll
        for (int t = 0; t < 4; t++) {
            int idx = tid + t * 256;
            int br = idx >> 5;
            int bc = idx & 31;
            cp_async16(&Bs[buf][br][bc * 4],
                       Bw + (size_t)(k0 + br) * OUT_F + bc * 4, 16);
        }
        cp_commit();
    };

    prefetch(0, 0);

    for (int kt = 0; kt < NITER; kt++) {
        const int buf = kt & 1;
        cp_wait<0>();
        __syncthreads();
        if (kt + 1 < NITER)
            prefetch(kt + 1, (kt + 1) & 1);

#pragma unroll
        for (int k8 = 0; k8 < 4; k8++) {
            const int k = k8 * 8;
            uint32_t afr[2][4];
#pragma unroll
            for (int mt = 0; mt < 2; mt++) {
                int rb = warp_m * 32 + mt * 16;
                afr[mt][0] = f2tf32u(As[buf][rb + g][k + t4]);
                afr[mt][1] = f2tf32u(As[buf][rb + g + 8][k + t4]);
                afr[mt][2] = f2tf32u(As[buf][rb + g][k + t4 + 4]);
                afr[mt][3] = f2tf32u(As[buf][rb + g + 8][k + t4 + 4]);
            }
#pragma unroll
            for (int nt = 0; nt < 8; nt++) {
                int nb = warp_n * 64 + nt * 8 + g;
                uint32_t b0 = f2tf32u(Bs[buf][k + t4][nb]);
                uint32_t b1 = f2tf32u(Bs[buf][k + t4 + 4][nb]);
                mma_tf32(c[0][nt], afr[0], b0, b1);
                mma_tf32(c[1][nt], afr[1], b0, b1);
            }
        }
    }

    // Epilogue: fp32 to C, fp16 to g_hh.
#pragma unroll
    for (int mt = 0; mt < 2; mt++) {
#pragma unroll
        for (int half = 0; half < 2; half++) {
            int row = row0 + warp_m * 32 + mt * 16 + g + half * 8;
            if (row < M) {
#pragma unroll
                for (int nt = 0; nt < 8; nt++) {
                    int col = warp_n * 64 + nt * 8 + 2 * t4;
                    float x = c[mt][nt][half * 2];
                    float y = c[mt][nt][half * 2 + 1];
                    *reinterpret_cast<float2*>(C + (size_t)row * OUT_F + col) =
                        make_float2(x, y);
                    __half2 hv = __floats2half2_rn(x, y);
                    *reinterpret_cast<__half2*>(g_hh + (size_t)row * OUT_F + col) = hv;
                }
            }
        }
    }
}

// ---------------------------------------------------------------------------
// Edge kernel: per warp, 24 consecutive edges; coalesced index load +
// shuffle distribution; each 16-lane half does 12 edges in 4 iters of 3
// (MLP=6). Reg-capped (256,6) + rolled j3 loop to restore occupancy.
// fp16 row gathers, fp32 math.
// ---------------------------------------------------------------------------
__device__ __forceinline__ float2 h2f(unsigned w) {
    __half2 b = *reinterpret_cast<__half2*>(&w);
    return __half22float2(b);
}

__device__ __forceinline__ float edge_dot(uint4 hu, uint4 hv,
                                          float4 a0, float4 a1) {
    float2 u0 = h2f(hu.x), u1 = h2f(hu.y), u2 = h2f(hu.z), u3 = h2f(hu.w);
    float2 v0 = h2f(hv.x), v1 = h2f(hv.y), v2 = h2f(hv.z), v3 = h2f(hv.w);
    return fabsf(u0.x - v0.x) * a0.x
         + fabsf(u0.y - v0.y) * a0.y
         + fabsf(u1.x - v1.x) * a0.z
         + fabsf(u1.y - v1.y) * a0.w
         + fabsf(u2.x - v2.x) * a1.x
         + fabsf(u2.y - v2.y) * a1.y
         + fabsf(u3.x - v3.x) * a1.z
         + fabsf(u3.y - v3.y) * a1.w;
}

__global__ __launch_bounds__(256, 6) void edge_kernel(
    const int* __restrict__ edge,         // [2,E] int32
    const float* __restrict__ a,          // [128]
    float* __restrict__ ew,               // [E]
    int E)
{
    const int lane = threadIdx.x & 31;
    const int half_id = lane >> 4;
    const int l16 = lane & 15;

    const float4 a0 = *(reinterpret_cast<const float4*>(a) + l16 * 2);
    const float4 a1 = *(reinterpret_cast<const float4*>(a) + l16 * 2 + 1);

    const int warps_total = (gridDim.x * blockDim.x) >> 5;
    const int warp = (blockIdx.x * blockDim.x + threadIdx.x) >> 5;

    for (int base = warp * EPW; base < E; base += warps_total * EPW) {
        // Coalesced index load: lanes 0..23 cover this warp's 24 edges.
        int u = 0, v = 0;
        int gidx = base + lane;
        if (lane < EPW && gidx < E) {
            u = edge[gidx];
            v = edge[(size_t)E + gidx];
        }

#pragma unroll 1
        for (int j3 = 0; j3 < 4; j3++) {
            const int s0 = half_id * 12 + j3 * 3;   // source lane of 1st edge
            const int e0 = base + s0;               // 3 consecutive edges

            int ua = __shfl_sync(0xFFFFFFFFu, u, s0);
            int va = __shfl_sync(0xFFFFFFFFu, v, s0);
            int ub = __shfl_sync(0xFFFFFFFFu, u, s0 + 1);
            int vb = __shfl_sync(0xFFFFFFFFu, v, s0 + 1);
            int uc = __shfl_sync(0xFFFFFFFFu, u, s0 + 2);
            int vc = __shfl_sync(0xFFFFFFFFu, v, s0 + 2);

            // Issue all 6 row gathers before computing (MLP=6)
            uint4 hua = *(reinterpret_cast<const uint4*>(g_hh + (size_t)ua * OUT_F) + l16);
            uint4 hva = *(reinterpret_cast<const uint4*>(g_hh + (size_t)va * OUT_F) + l16);
            uint4 hub = *(reinterpret_cast<const uint4*>(g_hh + (size_t)ub * OUT_F) + l16);
            uint4 hvb = *(reinterpret_cast<const uint4*>(g_hh + (size_t)vb * OUT_F) + l16);
            uint4 huc = *(reinterpret_cast<const uint4*>(g_hh + (size_t)uc * OUT_F) + l16);
            uint4 hvc = *(reinterpret_cast<const uint4*>(g_hh + (size_t)vc * OUT_F) + l16);

            float s1 = edge_dot(hua, hva, a0, a1);
            float s2 = edge_dot(hub, hvb, a0, a1);
            float s3 = edge_dot(huc, hvc, a0, a1);

#pragma unroll
            for (int off = 8; off > 0; off >>= 1) {
                s1 += __shfl_down_sync(0xFFFFFFFFu, s1, off, 16);
                s2 += __shfl_down_sync(0xFFFFFFFFu, s2, off, 16);
                s3 += __shfl_down_sync(0xFFFFFFFFu, s3, off, 16);
            }

            if (l16 == 0) {
                if (e0 < E)     ew[e0]     = fmaxf(s1, 0.0f);
                if (e0 + 1 < E) ew[e0 + 1] = fmaxf(s2, 0.0f);
                if (e0 + 2 < E) ew[e0 + 2] = fmaxf(s3, 0.0f);
            }
        }
    }
}

extern "C" void kernel_launch(void* const* d_in, const int* in_sizes, int n_in,
                              void* d_out, int out_size)
{
    const float* inputs = (const float*)d_in[0];
    const int* edge     = (const int*)d_in[1];
    const float* weight = (const float*)d_in[2];
    const float* a      = (const float*)d_in[3];

    int M = in_sizes[0] / IN_F;        // 100000
    int E = in_sizes[1] / 2;           // 1600000

    float* h  = (float*)d_out;                       // [M,128]
    float* ew = (float*)d_out + (size_t)M * OUT_F;   // [E]

    int gemm_blocks = (M + BM - 1) / BM;             // 782
    gemm_tf32_kernel<<<gemm_blocks, 256>>>(inputs, weight, h, M);

    edge_kernel<<<4096, 256>>>(edge, a, ew, E);
}

// round 16
// speedup vs baseline: 1.1057x; 1.0118x over previous
#include <cuda_runtime.h>
#include <cuda_fp16.h>
#include <cstdint>

#define IN_F 256
#define OUT_F 128
#define MAX_NODES 100000
#define BM 128
#define BN 128
#define BK 32
#define EPW 24   // edges per warp per grid pass (12 per 16-lane half)

__device__ __half g_hh[(size_t)MAX_NODES * OUT_F];

__device__ __forceinline__ uint32_t f2tf32u(float x) {
    uint32_t o;
    asm("cvt.rna.tf32.f32 %0, %1;" : "=r"(o) : "f"(x));
    return o;
}

__device__ __forceinline__ void mma_tf32(float* c, const uint32_t* a,
                                         uint32_t b0, uint32_t b1) {
    asm volatile(
        "mma.sync.aligned.m16n8k8.row.col.f32.tf32.tf32.f32 "
        "{%0,%1,%2,%3}, {%4,%5,%6,%7}, {%8,%9}, {%0,%1,%2,%3};\n"
        : "+f"(c[0]), "+f"(c[1]), "+f"(c[2]), "+f"(c[3])
        : "r"(a[0]), "r"(a[1]), "r"(a[2]), "r"(a[3]), "r"(b0), "r"(b1));
}

__device__ __forceinline__ void cp_async16(void* smem_dst, const void* gsrc, int src_bytes) {
    uint32_t daddr = (uint32_t)__cvta_generic_to_shared(smem_dst);
    asm volatile("cp.async.ca.shared.global [%0], [%1], 16, %2;\n"
                 :: "r"(daddr), "l"(gsrc), "r"(src_bytes));
}
__device__ __forceinline__ void cp_commit() {
    asm volatile("cp.async.commit_group;\n" ::: "memory");
}
template <int N>
__device__ __forceinline__ void cp_wait() {
    asm volatile("cp.async.wait_group %0;\n" :: "n"(N) : "memory");
}

// ---------------------------------------------------------------------------
// GEMM (R13 form, ~62us): tf32 mma.sync, 2-stage cp.async, one sync/k-iter.
// ---------------------------------------------------------------------------
__global__ __launch_bounds__(256) void gemm_tf32_kernel(
    const float* __restrict__ A,   // [M, 256]
    const float* __restrict__ Bw,  // [256, 128]
    float* __restrict__ C,         // [M, 128]
    int M)
{
    __shared__ float As[2][BM][BK + 4];
    __shared__ float Bs[2][BK][BN + 8];

    const int tid = threadIdx.x;
    const int wid = tid >> 5;
    const int lane = tid & 31;
    const int g = lane >> 2;
    const int t4 = lane & 3;
    const int warp_m = wid & 3;
    const int warp_n = wid >> 2;
    const int row0 = blockIdx.x * BM;

    float c[2][8][4];
#pragma unroll
    for (int mt = 0; mt < 2; mt++)
#pragma unroll
        for (int nt = 0; nt < 8; nt++)
#pragma unroll
            for (int i = 0; i < 4; i++) c[mt][nt][i] = 0.0f;

    const int NITER = IN_F / BK;  // 8

    auto prefetch = [&](int kt, int buf) {
        const int k0 = kt * BK;
#pragma unroll
        for (int t = 0; t < 4; t++) {
            int idx = tid + t * 256;
            int ar = idx >> 3;
            int ac = idx & 7;
            int grow = row0 + ar;
            int ok = (grow < M) ? 16 : 0;
            int gc = (grow < M) ? grow : 0;
            cp_async16(&As[buf][ar][ac * 4],
                       A + (size_t)gc * IN_F + k0 + ac * 4, ok);
        }
#pragma unroll
        for (int t = 0; t < 4; t++) {
            int idx = tid + t * 256;
            int br = idx >> 5;
            int bc = idx & 31;
            cp_async16(&Bs[buf][br][bc * 4],
                       Bw + (size_t)(k0 + br) * OUT_F + bc * 4, 16);
        }
        cp_commit();
    };

    prefetch(0, 0);

    for (int kt = 0; kt < NITER; kt++) {
        const int buf = kt & 1;
        cp_wait<0>();
        __syncthreads();
        if (kt + 1 < NITER)
            prefetch(kt + 1, (kt + 1) & 1);

#pragma unroll
        for (int k8 = 0; k8 < 4; k8++) {
            const int k = k8 * 8;
            uint32_t afr[2][4];
#pragma unroll
            for (int mt = 0; mt < 2; mt++) {
                int rb = warp_m * 32 + mt * 16;
                afr[mt][0] = f2tf32u(As[buf][rb + g][k + t4]);
                afr[mt][1] = f2tf32u(As[buf][rb + g + 8][k + t4]);
                afr[mt][2] = f2tf32u(As[buf][rb + g][k + t4 + 4]);
                afr[mt][3] = f2tf32u(As[buf][rb + g + 8][k + t4 + 4]);
            }
#pragma unroll
            for (int nt = 0; nt < 8; nt++) {
                int nb = warp_n * 64 + nt * 8 + g;
                uint32_t b0 = f2tf32u(Bs[buf][k + t4][nb]);
                uint32_t b1 = f2tf32u(Bs[buf][k + t4 + 4][nb]);
                mma_tf32(c[0][nt], afr[0], b0, b1);
                mma_tf32(c[1][nt], afr[1], b0, b1);
            }
        }
    }

    // Epilogue: fp32 to C, fp16 to g_hh.
#pragma unroll
    for (int mt = 0; mt < 2; mt++) {
#pragma unroll
        for (int half = 0; half < 2; half++) {
            int row = row0 + warp_m * 32 + mt * 16 + g + half * 8;
            if (row < M) {
#pragma unroll
                for (int nt = 0; nt < 8; nt++) {
                    int col = warp_n * 64 + nt * 8 + 2 * t4;
                    float x = c[mt][nt][half * 2];
                    float y = c[mt][nt][half * 2 + 1];
                    *reinterpret_cast<float2*>(C + (size_t)row * OUT_F + col) =
                        make_float2(x, y);
                    __half2 hv = __floats2half2_rn(x, y);
                    *reinterpret_cast<__half2*>(g_hh + (size_t)row * OUT_F + col) = hv;
                }
            }
        }
    }
}

// ---------------------------------------------------------------------------
// Edge kernel: per warp, 24 consecutive edges; coalesced index load +
// shuffle distribution; 16-lane half does 12 edges in 4 iters of 3 (MLP=6).
// Butterfly reduction (all lanes get sum) -> park per-lane -> ONE coalesced
// 24-float output store per warp pass (kills 24 scattered store wavefronts).
// ---------------------------------------------------------------------------
__device__ __forceinline__ float2 h2f(unsigned w) {
    __half2 b = *reinterpret_cast<__half2*>(&w);
    return __half22float2(b);
}

__device__ __forceinline__ float edge_dot(uint4 hu, uint4 hv,
                                          float4 a0, float4 a1) {
    float2 u0 = h2f(hu.x), u1 = h2f(hu.y), u2 = h2f(hu.z), u3 = h2f(hu.w);
    float2 v0 = h2f(hv.x), v1 = h2f(hv.y), v2 = h2f(hv.z), v3 = h2f(hv.w);
    return fabsf(u0.x - v0.x) * a0.x
         + fabsf(u0.y - v0.y) * a0.y
         + fabsf(u1.x - v1.x) * a0.z
         + fabsf(u1.y - v1.y) * a0.w
         + fabsf(u2.x - v2.x) * a1.x
         + fabsf(u2.y - v2.y) * a1.y
         + fabsf(u3.x - v3.x) * a1.z
         + fabsf(u3.y - v3.y) * a1.w;
}

__global__ __launch_bounds__(256, 6) void edge_kernel(
    const int* __restrict__ edge,         // [2,E] int32
    const float* __restrict__ a,          // [128]
    float* __restrict__ ew,               // [E]
    int E)
{
    const int lane = threadIdx.x & 31;
    const int half_id = lane >> 4;
    const int l16 = lane & 15;

    const float4 a0 = *(reinterpret_cast<const float4*>(a) + l16 * 2);
    const float4 a1 = *(reinterpret_cast<const float4*>(a) + l16 * 2 + 1);

    const int warps_total = (gridDim.x * blockDim.x) >> 5;
    const int warp = (blockIdx.x * blockDim.x + threadIdx.x) >> 5;

    for (int base = warp * EPW; base < E; base += warps_total * EPW) {
        // Coalesced index load: lanes 0..23 cover this warp's 24 edges.
        int u = 0, v = 0;
        int gidx = base + lane;
        if (lane < EPW && gidx < E) {
            u = edge[gidx];
            v = edge[(size_t)E + gidx];
        }

        float out = 0.0f;   // this lane's parked result (edge base + half*12 + l16)

#pragma unroll 1
        for (int j3 = 0; j3 < 4; j3++) {
            const int s0 = half_id * 12 + j3 * 3;   // source lane of 1st edge

            int ua = __shfl_sync(0xFFFFFFFFu, u, s0);
            int va = __shfl_sync(0xFFFFFFFFu, v, s0);
            int ub = __shfl_sync(0xFFFFFFFFu, u, s0 + 1);
            int vb = __shfl_sync(0xFFFFFFFFu, v, s0 + 1);
            int uc = __shfl_sync(0xFFFFFFFFu, u, s0 + 2);
            int vc = __shfl_sync(0xFFFFFFFFu, v, s0 + 2);

            // Issue all 6 row gathers before computing (MLP=6)
            uint4 hua = *(reinterpret_cast<const uint4*>(g_hh + (size_t)ua * OUT_F) + l16);
            uint4 hva = *(reinterpret_cast<const uint4*>(g_hh + (size_t)va * OUT_F) + l16);
            uint4 hub = *(reinterpret_cast<const uint4*>(g_hh + (size_t)ub * OUT_F) + l16);
            uint4 hvb = *(reinterpret_cast<const uint4*>(g_hh + (size_t)vb * OUT_F) + l16);
            uint4 huc = *(reinterpret_cast<const uint4*>(g_hh + (size_t)uc * OUT_F) + l16);
            uint4 hvc = *(reinterpret_cast<const uint4*>(g_hh + (size_t)vc * OUT_F) + l16);

            float s1 = edge_dot(hua, hva, a0, a1);
            float s2 = edge_dot(hub, hvb, a0, a1);
            float s3 = edge_dot(huc, hvc, a0, a1);

            // Butterfly reduction within 16-lane half: every lane gets the sum
#pragma unroll
            for (int off = 8; off > 0; off >>= 1) {
                s1 += __shfl_xor_sync(0xFFFFFFFFu, s1, off, 16);
                s2 += __shfl_xor_sync(0xFFFFFFFFu, s2, off, 16);
                s3 += __shfl_xor_sync(0xFFFFFFFFu, s3, off, 16);
            }

            // Park: lane l16 owns edge offset half*12 + l16
            const int j0 = j3 * 3;
            if (l16 == j0)     out = s1;
            if (l16 == j0 + 1) out = s2;
            if (l16 == j0 + 2) out = s3;
        }

        // One coalesced store: lanes {0..11, 16..27} write 24 contiguous floats
        const int off = half_id * 12 + l16;
        if (l16 < 12 && base + off < E)
            ew[base + off] = fmaxf(out, 0.0f);
    }
}

extern "C" void kernel_launch(void* const* d_in, const int* in_sizes, int n_in,
                              void* d_out, int out_size)
{
    const float* inputs = (const float*)d_in[0];
    const int* edge     = (const int*)d_in[1];
    const float* weight = (const float*)d_in[2];
    const float* a      = (const float*)d_in[3];

    int M = in_sizes[0] / IN_F;        // 100000
    int E = in_sizes[1] / 2;           // 1600000

    float* h  = (float*)d_out;                       // [M,128]
    float* ew = (float*)d_out + (size_t)M * OUT_F;   // [E]

    int gemm_blocks = (M + BM - 1) / BM;             // 782
    gemm_tf32_kernel<<<gemm_blocks, 256>>>(inputs, weight, h, M);

    edge_kernel<<<4096, 256>>>(edge, a, ew, E);
}